// round 3
// baseline (speedup 1.0000x reference)
#include <cuda_runtime.h>
#include <cuda_bf16.h>

typedef unsigned long long ull;

// ---------------- scratch (device globals; no allocation allowed) ----------------
__device__ float d_UV[4096 * 1024];   // [row=b*32+p][k] : k<512 -> U+g1_b, k>=512 -> V
__device__ float d_glbl[128 * 256];
__device__ float d_xgp[8 * 128 * 256]; // per-atile partial sums of h4
__device__ float d_xf[128 * 512];      // concat [x_f, glbl]
__device__ float d_z2[128 * 256];
__device__ float d_y2[128 * 256];
__device__ float d_z3[128 * 128];

// ---------------- f32x2 helpers (Blackwell packed fp32, 2 MAC / inst) ----------------
__device__ __forceinline__ void ffma2(ull &d, ull a, ull b) {
    asm("fma.rn.f32x2 %0, %1, %2, %0;" : "+l"(d) : "l"(a), "l"(b));
}
__device__ __forceinline__ ull splat2(float x) {
    ull r; asm("mov.b64 %0, {%1, %1};" : "=l"(r) : "f"(x)); return r;
}
__device__ __forceinline__ float2 unpack2(ull v) {
    float2 f; asm("mov.b64 {%0, %1}, %2;" : "=f"(f.x), "=f"(f.y) : "l"(v)); return f;
}
__device__ __forceinline__ ull pack2(float lo, float hi) {
    ull r; asm("mov.b64 %0, {%1, %2};" : "=l"(r) : "f"(lo), "f"(hi)); return r;
}

// 128x256 tile micro-kernel over a 32-k chunk.
// A k-major in smem: Asrc[kk*astride + row], rows row-paired into f32x2 (astride even).
// W k-major padded:  Ws[kk*257 + m]  (conflict-free lane-varying reads).
// Thread (ty=t/32, tx=t%32): rows ty*8 .. ty*8+7 (4 pairs), cols tx+32*j (8).
__device__ __forceinline__ void micro32(const float* __restrict__ Asrc, int astride,
                                        const float* __restrict__ Ws, int ty, int tx,
                                        ull acc[4][8]) {
#pragma unroll 8
    for (int kk = 0; kk < 32; ++kk) {
        ull a2[4];
#pragma unroll
        for (int p = 0; p < 4; ++p)
            a2[p] = *reinterpret_cast<const ull*>(Asrc + kk * astride + ty * 8 + 2 * p);
#pragma unroll
        for (int j = 0; j < 8; ++j) {
            ull w2 = splat2(Ws[kk * 257 + tx + 32 * j]);
#pragma unroll
            for (int p = 0; p < 4; ++p) ffma2(acc[p][j], a2[p], w2);
        }
    }
}

__device__ __forceinline__ void zero_acc(ull acc[4][8]) {
#pragma unroll
    for (int p = 0; p < 4; ++p)
#pragma unroll
        for (int j = 0; j < 8; ++j) acc[p][j] = 0ull;
}

// ---------------- glbl: 2x2 avgpool then 1x1 conv (linear => commutes) ----------------
__global__ void glbl_kernel(const float* __restrict__ x, const float* __restrict__ convw,
                            const float* __restrict__ convb) {
    __shared__ float sx[128 * 32];    // [cl][hw]
    __shared__ float sw[128 * 33];    // [cl][o], pad 33
    __shared__ float sxp[128 * 8];    // pooled [cl][s]
    int b = blockIdx.x, t = threadIdx.x;     // 256 threads
    int o = t >> 3, s = t & 7;
    float acc = 0.f;
    for (int c0 = 0; c0 < 2048; c0 += 128) {
        __syncthreads();
#pragma unroll
        for (int i = 0; i < 16; ++i) {
            int e = i * 256 + t; int hw = e & 31, cl = e >> 5;
            sx[cl * 32 + hw] = x[(b * 2048 + c0 + cl) * 32 + hw];
        }
#pragma unroll
        for (int i = 0; i < 16; ++i) {
            int e = i * 256 + t; int cl = e & 127, oo = e >> 7;
            sw[cl * 33 + oo] = convw[oo * 2048 + c0 + cl];
        }
        __syncthreads();
#pragma unroll
        for (int i = 0; i < 4; ++i) {
            int e = i * 256 + t; int ss = e & 7, cl = e >> 3;
            int base = cl * 32 + 8 * (ss >> 1) + 2 * (ss & 1);
            sxp[cl * 8 + ss] = sx[base] + sx[base + 1] + sx[base + 4] + sx[base + 5];
        }
        __syncthreads();
#pragma unroll 8
        for (int cl = 0; cl < 128; ++cl)
            acc += sw[cl * 33 + o] * sxp[cl * 8 + s];
    }
    d_glbl[b * 256 + o * 8 + s] = 0.25f * acc + convb[o];
}

// ---------------- UV GEMM: (4096x2048) x (2048x1024) -> d_UV (g1_b folded into U) ----------------
__global__ __launch_bounds__(512, 1)
void uv_gemm_kernel(const float* __restrict__ x, const float* __restrict__ g1w,
                    const float* __restrict__ g1b) {
    extern __shared__ float sm[];
    float* As = sm;                  // [32][130]
    float* Ws = sm + 32 * 130;       // [32][257]
    int t = threadIdx.x;
    int ty = t >> 5, tx = t & 31;
    int m0 = blockIdx.x * 128;       // 32 m-tiles
    int n0 = blockIdx.y * 256;       // 4 n-tiles
    ull acc[4][8];
    zero_acc(acc);

    for (int kc = 0; kc < 64; ++kc) {
        __syncthreads();
        int kb = kc * 32;
        // A tile: A[row,k] = x[(b*2048+k)*32 + p]  (coalesced: lanes -> consecutive p)
#pragma unroll
        for (int i = 0; i < 8; ++i) {
            int e = i * 512 + t;
            int mloc = e & 127, kl = e >> 7;
            int row = m0 + mloc;
            As[kl * 130 + mloc] = x[((row >> 5) * 2048 + kb + kl) * 32 + (row & 31)];
        }
        // W tile: cols<512 from Wp=g1w[:, :2048], cols>=512 from Wa=g1w[:, 2048:]
#pragma unroll
        for (int i = 0; i < 16; ++i) {
            int e = i * 512 + t;
            int kk = e & 31, n = e >> 5;
            int ng = n0 + n;
            float w = (ng < 512) ? g1w[ng * 4096 + kb + kk]
                                 : g1w[(ng - 512) * 4096 + 2048 + kb + kk];
            Ws[kk * 257 + n] = w;
        }
        __syncthreads();
        micro32(As, 130, Ws, ty, tx, acc);
    }
#pragma unroll
    for (int j = 0; j < 8; ++j) {
        int col = n0 + tx + 32 * j;
        float bias = (col < 512) ? g1b[col] : 0.f;   // fold g1_b into U
#pragma unroll
        for (int p = 0; p < 4; ++p) {
            float2 v = unpack2(acc[p][j]);
            int r = m0 + ty * 8 + 2 * p;
            d_UV[r * 1024 + col]       = v.x + bias;
            d_UV[(r + 1) * 1024 + col] = v.y + bias;
        }
    }
}

// ---------------- pairwise MLP: layers 2,3,4 + row-sum -> d_xgp ----------------
__global__ __launch_bounds__(512, 1)
void pairwise_kernel(const float* __restrict__ g2w, const float* __restrict__ g2b,
                     const float* __restrict__ g3w, const float* __restrict__ g3b,
                     const float* __restrict__ g4w, const float* __restrict__ g4b) {
    extern __shared__ float sm[];
    float* As   = sm;                       // [32][130]   (+ reduction scratch [16][256])
    float* Ws   = sm + 32 * 130;            // [32][257]
    float* Hbuf = sm + 32 * 130 + 32 * 257; // [256 cols][130 rows]
    int t = threadIdx.x;
    int ty = t >> 5, tx = t & 31;
    int atile = blockIdx.x;                 // 8 a-tiles of 4
    int b = blockIdx.y;                     // 128 batches
    int a0 = atile * 4;

    ull acc[4][8];

    // ----- layer 2: rows = relu(U[p]+V[a]) (built on the fly), k = 512 -----
    zero_acc(acc);
    for (int kc = 0; kc < 16; ++kc) {
        __syncthreads();
        int kb = kc * 32;
#pragma unroll
        for (int i = 0; i < 8; ++i) {
            int e = i * 512 + t;
            int kk = e & 31, row = e >> 5;            // lanes -> consecutive kk (coalesced)
            int p = row & 31, a = a0 + (row >> 5);
            float u = d_UV[(b * 32 + p) * 1024 + kb + kk];
            float v = d_UV[(b * 32 + a) * 1024 + 512 + kb + kk];
            As[kk * 130 + row] = fmaxf(u + v, 0.f);
        }
#pragma unroll
        for (int i = 0; i < 16; ++i) {
            int e = i * 512 + t;
            int kk = e & 31, m = e >> 5;
            Ws[kk * 257 + m] = g2w[m * 512 + kb + kk];
        }
        __syncthreads();
        micro32(As, 130, Ws, ty, tx, acc);
    }
    __syncthreads();
#pragma unroll
    for (int j = 0; j < 8; ++j) {
        int col = tx + 32 * j;
        float bias = g2b[col];
#pragma unroll
        for (int p = 0; p < 4; ++p) {
            float2 v = unpack2(acc[p][j]);
            *reinterpret_cast<ull*>(Hbuf + col * 130 + ty * 8 + 2 * p) =
                pack2(fmaxf(v.x + bias, 0.f), fmaxf(v.y + bias, 0.f));
        }
    }

    // ----- layer 3: A = Hbuf (k-major), k = 256, output overwrites Hbuf after full k -----
    zero_acc(acc);
    for (int kc = 0; kc < 8; ++kc) {
        __syncthreads();
        int kb = kc * 32;
#pragma unroll
        for (int i = 0; i < 16; ++i) {
            int e = i * 512 + t;
            int kk = e & 31, m = e >> 5;
            Ws[kk * 257 + m] = g3w[m * 256 + kb + kk];
        }
        __syncthreads();
        micro32(Hbuf + kb * 130, 130, Ws, ty, tx, acc);
    }
    __syncthreads();
#pragma unroll
    for (int j = 0; j < 8; ++j) {
        int col = tx + 32 * j;
        float bias = g3b[col];
#pragma unroll
        for (int p = 0; p < 4; ++p) {
            float2 v = unpack2(acc[p][j]);
            *reinterpret_cast<ull*>(Hbuf + col * 130 + ty * 8 + 2 * p) =
                pack2(fmaxf(v.x + bias, 0.f), fmaxf(v.y + bias, 0.f));
        }
    }

    // ----- layer 4: same, but reduce rows instead of storing -----
    zero_acc(acc);
    for (int kc = 0; kc < 8; ++kc) {
        __syncthreads();
        int kb = kc * 32;
#pragma unroll
        for (int i = 0; i < 16; ++i) {
            int e = i * 512 + t;
            int kk = e & 31, m = e >> 5;
            Ws[kk * 257 + m] = g4w[m * 256 + kb + kk];
        }
        __syncthreads();
        micro32(Hbuf + kb * 130, 130, Ws, ty, tx, acc);
    }
    // per-thread partial row-sum of relu(acc + g4_b)
#pragma unroll
    for (int j = 0; j < 8; ++j) {
        int col = tx + 32 * j;
        float bias = g4b[col];
        float s = 0.f;
#pragma unroll
        for (int p = 0; p < 4; ++p) {
            float2 v = unpack2(acc[p][j]);
            s += fmaxf(v.x + bias, 0.f) + fmaxf(v.y + bias, 0.f);
        }
        As[ty * 256 + col] = s;   // reuse As as [16][256] scratch
    }
    __syncthreads();
    if (t < 256) {
        float s = 0.f;
#pragma unroll
        for (int ty2 = 0; ty2 < 16; ++ty2) s += As[ty2 * 256 + t];
        d_xgp[(atile * 128 + b) * 256 + t] = s;
    }
}

// ---------------- head ----------------
__global__ void f1_kernel(const float* __restrict__ f1w, const float* __restrict__ f1b) {
    __shared__ float sxg[256];
    int b = blockIdx.x, t = threadIdx.x;   // 256 threads
    float s = 0.f;
#pragma unroll
    for (int at = 0; at < 8; ++at) s += d_xgp[(at * 128 + b) * 256 + t];
    sxg[t] = s;
    __syncthreads();
    float acc = f1b[t];
    const float4* wr = reinterpret_cast<const float4*>(f1w + t * 256);
#pragma unroll 8
    for (int k4 = 0; k4 < 64; ++k4) {
        float4 w = wr[k4];
        acc += sxg[4 * k4] * w.x + sxg[4 * k4 + 1] * w.y
             + sxg[4 * k4 + 2] * w.z + sxg[4 * k4 + 3] * w.w;
    }
    d_xf[b * 512 + t]       = fmaxf(acc, 0.f);
    d_xf[b * 512 + 256 + t] = d_glbl[b * 256 + t];
}

__global__ void fc2_kernel(const float* __restrict__ w, const float* __restrict__ bb) {
    __shared__ float sx[512];
    int b = blockIdx.x, t = threadIdx.x;   // 256 threads
    sx[t] = d_xf[b * 512 + t];
    sx[t + 256] = d_xf[b * 512 + 256 + t];
    __syncthreads();
    float acc = bb[t];
    const float4* wr = reinterpret_cast<const float4*>(w + t * 512);
#pragma unroll 8
    for (int k4 = 0; k4 < 128; ++k4) {
        float4 wv = wr[k4];
        acc += sx[4 * k4] * wv.x + sx[4 * k4 + 1] * wv.y
             + sx[4 * k4 + 2] * wv.z + sx[4 * k4 + 3] * wv.w;
    }
    d_z2[b * 256 + t] = acc;
}

__global__ void bn2_kernel(const float* __restrict__ g, const float* __restrict__ bb) {
    __shared__ float red[128];
    int o = blockIdx.x, r = threadIdx.x;   // 256 cols x 128 rows
    float v = d_z2[r * 256 + o];
    red[r] = v;
    __syncthreads();
    for (int s = 64; s > 0; s >>= 1) { if (r < s) red[r] += red[r + s]; __syncthreads(); }
    float mu = red[0] * (1.f / 128.f);
    __syncthreads();
    float dlt = v - mu;
    red[r] = dlt * dlt;
    __syncthreads();
    for (int s = 64; s > 0; s >>= 1) { if (r < s) red[r] += red[r + s]; __syncthreads(); }
    float var = red[0] * (1.f / 128.f);
    d_y2[r * 256 + o] = fmaxf(dlt * rsqrtf(var + 1e-5f) * g[o] + bb[o], 0.f);
}

__global__ void fc3_kernel(const float* __restrict__ w, const float* __restrict__ bb) {
    __shared__ float sx[256];
    int b = blockIdx.x, t = threadIdx.x;   // 128 threads
    sx[t] = d_y2[b * 256 + t];
    sx[t + 128] = d_y2[b * 256 + 128 + t];
    __syncthreads();
    float acc = bb[t];
    const float4* wr = reinterpret_cast<const float4*>(w + t * 256);
#pragma unroll 8
    for (int k4 = 0; k4 < 64; ++k4) {
        float4 wv = wr[k4];
        acc += sx[4 * k4] * wv.x + sx[4 * k4 + 1] * wv.y
             + sx[4 * k4 + 2] * wv.z + sx[4 * k4 + 3] * wv.w;
    }
    d_z3[b * 128 + t] = acc;
}

__global__ void bn3_kernel(const float* __restrict__ g, const float* __restrict__ bb,
                           float* __restrict__ out) {
    __shared__ float red[128];
    int o = blockIdx.x, r = threadIdx.x;   // 128 cols x 128 rows
    float v = d_z3[r * 128 + o];
    red[r] = v;
    __syncthreads();
    for (int s = 64; s > 0; s >>= 1) { if (r < s) red[r] += red[r + s]; __syncthreads(); }
    float mu = red[0] * (1.f / 128.f);
    __syncthreads();
    float dlt = v - mu;
    red[r] = dlt * dlt;
    __syncthreads();
    for (int s = 64; s > 0; s >>= 1) { if (r < s) red[r] += red[r + s]; __syncthreads(); }
    float var = red[0] * (1.f / 128.f);
    out[r * 128 + o] = fmaxf(dlt * rsqrtf(var + 1e-5f) * g[o] + bb[o], 0.f);
}

// ---------------- launch ----------------
extern "C" void kernel_launch(void* const* d_in, const int* in_sizes, int n_in,
                              void* d_out, int out_size) {
    const float* x      = (const float*)d_in[0];
    const float* conv_w = (const float*)d_in[1];
    const float* conv_b = (const float*)d_in[2];
    const float* g1_w   = (const float*)d_in[3];
    const float* g1_b   = (const float*)d_in[4];
    const float* g2_w   = (const float*)d_in[5];
    const float* g2_b   = (const float*)d_in[6];
    const float* g3_w   = (const float*)d_in[7];
    const float* g3_b   = (const float*)d_in[8];
    const float* g4_w   = (const float*)d_in[9];
    const float* g4_b   = (const float*)d_in[10];
    const float* f1_w   = (const float*)d_in[11];
    const float* f1_b   = (const float*)d_in[12];
    const float* fc2_w  = (const float*)d_in[13];
    const float* fc2_b  = (const float*)d_in[14];
    const float* bn2_g  = (const float*)d_in[15];
    const float* bn2_b  = (const float*)d_in[16];
    const float* fc3_w  = (const float*)d_in[17];
    const float* fc3_b  = (const float*)d_in[18];
    const float* bn3_g  = (const float*)d_in[19];
    const float* bn3_b  = (const float*)d_in[20];
    float* out = (float*)d_out;

    const int UV_SMEM = (32 * 130 + 32 * 257) * 4;              // 49536 B
    const int PW_SMEM = (32 * 130 + 32 * 257 + 256 * 130) * 4;  // 182656 B
    cudaFuncSetAttribute(uv_gemm_kernel, cudaFuncAttributeMaxDynamicSharedMemorySize, UV_SMEM);
    cudaFuncSetAttribute(pairwise_kernel, cudaFuncAttributeMaxDynamicSharedMemorySize, PW_SMEM);

    glbl_kernel<<<128, 256>>>(x, conv_w, conv_b);
    uv_gemm_kernel<<<dim3(32, 4), 512, UV_SMEM>>>(x, g1_w, g1_b);
    pairwise_kernel<<<dim3(8, 128), 512, PW_SMEM>>>(g2_w, g2_b, g3_w, g3_b, g4_w, g4_b);
    f1_kernel<<<128, 256>>>(f1_w, f1_b);
    fc2_kernel<<<128, 256>>>(fc2_w, fc2_b);
    bn2_kernel<<<256, 128>>>(bn2_g, bn2_b);
    fc3_kernel<<<128, 128>>>(fc3_w, fc3_b);
    bn3_kernel<<<128, 128>>>(bn3_g, bn3_b, out);
}

// round 5
// speedup vs baseline: 1.0081x; 1.0081x over previous
#include <cuda_runtime.h>
#include <cuda_bf16.h>
#include <cstdint>

typedef unsigned long long ull;

// ---------------- scratch (device globals; no allocation allowed) ----------------
__device__ float d_UV[4096 * 1024];    // [row=b*32+p][k] : k<512 -> U+g1_b, k>=512 -> V
__device__ float d_glbl[128 * 256];
__device__ float d_xgp[8 * 128 * 256]; // per-atile partial sums of h4
__device__ float d_z2[128 * 256];
__device__ float d_y2[128 * 256];
__device__ float d_z3[128 * 128];

// ---------------- f32x2 helpers (Blackwell packed fp32, 2 MAC / inst) ----------------
__device__ __forceinline__ void ffma2(ull &d, ull a, ull b) {
    asm("fma.rn.f32x2 %0, %1, %2, %0;" : "+l"(d) : "l"(a), "l"(b));
}
__device__ __forceinline__ ull splat2(float x) {
    ull r; asm("mov.b64 %0, {%1, %1};" : "=l"(r) : "f"(x)); return r;
}
__device__ __forceinline__ float2 unpack2(ull v) {
    float2 f; asm("mov.b64 {%0, %1}, %2;" : "=f"(f.x), "=f"(f.y) : "l"(v)); return f;
}
__device__ __forceinline__ ull pack2(float lo, float hi) {
    ull r; asm("mov.b64 %0, {%1, %2};" : "=l"(r) : "f"(lo), "f"(hi)); return r;
}

// ---------------- cp.async helpers ----------------
__device__ __forceinline__ void cp4(float* smem_dst, const float* gsrc) {
    unsigned int a = (unsigned int)__cvta_generic_to_shared(smem_dst);
    asm volatile("cp.async.ca.shared.global [%0], [%1], 4;" :: "r"(a), "l"(gsrc));
}
#define CP_COMMIT() asm volatile("cp.async.commit_group;" ::: "memory")
#define CP_WAIT1()  asm volatile("cp.async.wait_group 1;" ::: "memory")
#define CP_WAIT0()  asm volatile("cp.async.wait_group 0;" ::: "memory")

// W chunk: 32k x 256n, dst Ws[kk*257 + m]  (lanes -> consecutive kk: coalesced gmem,
// stride-257 smem rows -> conflict-free banks)
__device__ __forceinline__ void cp_w_chunk(float* Wbuf, const float* __restrict__ gw,
                                           int ldk, int kb, int t) {
#pragma unroll
    for (int i = 0; i < 16; ++i) {
        int e = i * 512 + t;
        int kk = e & 31, m = e >> 5;
        cp4(Wbuf + kk * 257 + m, gw + m * ldk + kb + kk);
    }
}

// 128x256 tile micro-kernel over a 32-k chunk.
// A k-major in smem: Asrc[kk*astride + row], rows row-paired into f32x2 (astride even).
// W k-major padded:  Ws[kk*257 + m].
// Thread (ty=t/32, tx=t%32): rows ty*8 .. ty*8+7 (4 pairs), cols tx+32*j (8).
__device__ __forceinline__ void micro32(const float* __restrict__ Asrc, int astride,
                                        const float* __restrict__ Ws, int ty, int tx,
                                        ull acc[4][8]) {
#pragma unroll 8
    for (int kk = 0; kk < 32; ++kk) {
        ull a2[4];
#pragma unroll
        for (int p = 0; p < 4; ++p)
            a2[p] = *reinterpret_cast<const ull*>(Asrc + kk * astride + ty * 8 + 2 * p);
#pragma unroll
        for (int j = 0; j < 8; ++j) {
            ull w2 = splat2(Ws[kk * 257 + tx + 32 * j]);
#pragma unroll
            for (int p = 0; p < 4; ++p) ffma2(acc[p][j], a2[p], w2);
        }
    }
}

__device__ __forceinline__ void zero_acc(ull acc[4][8]) {
#pragma unroll
    for (int p = 0; p < 4; ++p)
#pragma unroll
        for (int j = 0; j < 8; ++j) acc[p][j] = 0ull;
}

// ---------------- glbl: 2x2 avgpool then 1x1 conv (linear => commutes) ----------------
__global__ void glbl_kernel(const float* __restrict__ x, const float* __restrict__ convw,
                            const float* __restrict__ convb) {
    __shared__ float sx[128 * 32];
    __shared__ float sw[128 * 33];
    __shared__ float sxp[128 * 8];
    int b = blockIdx.x, t = threadIdx.x;     // 256 threads
    int o = t >> 3, s = t & 7;
    float acc = 0.f;
    for (int c0 = 0; c0 < 2048; c0 += 128) {
        __syncthreads();
#pragma unroll
        for (int i = 0; i < 16; ++i) {
            int e = i * 256 + t; int hw = e & 31, cl = e >> 5;
            sx[cl * 32 + hw] = x[(b * 2048 + c0 + cl) * 32 + hw];
        }
#pragma unroll
        for (int i = 0; i < 16; ++i) {
            int e = i * 256 + t; int cl = e & 127, oo = e >> 7;
            sw[cl * 33 + oo] = convw[oo * 2048 + c0 + cl];
        }
        __syncthreads();
#pragma unroll
        for (int i = 0; i < 4; ++i) {
            int e = i * 256 + t; int ss = e & 7, cl = e >> 3;
            int base = cl * 32 + 8 * (ss >> 1) + 2 * (ss & 1);
            sxp[cl * 8 + ss] = sx[base] + sx[base + 1] + sx[base + 4] + sx[base + 5];
        }
        __syncthreads();
#pragma unroll 8
        for (int cl = 0; cl < 128; ++cl)
            acc += sw[cl * 33 + o] * sxp[cl * 8 + s];
    }
    d_glbl[b * 256 + o * 8 + s] = 0.25f * acc + convb[o];
}

// ---------------- UV GEMM: (4096x2048) x (2048x1024) -> d_UV, cp.async depth-2 ----------------
__device__ __forceinline__ void uv_issue(float* As, float* Ws, const float* __restrict__ x,
                                         const float* __restrict__ g1w,
                                         int m0, int n0, int kc, int t) {
    int kb = kc * 32;
    float* Ab = As + (kc & 1) * 4160;
    float* Wb = Ws + (kc & 1) * 8224;
#pragma unroll
    for (int i = 0; i < 8; ++i) {
        int e = i * 512 + t;
        int mloc = e & 127, kl = e >> 7;
        int row = m0 + mloc;
        cp4(Ab + kl * 130 + mloc, x + ((row >> 5) * 2048 + kb + kl) * 32 + (row & 31));
    }
#pragma unroll
    for (int i = 0; i < 16; ++i) {
        int e = i * 512 + t;
        int kk = e & 31, n = e >> 5;
        int ng = n0 + n;
        const float* src = (ng < 512) ? (g1w + ng * 4096 + kb + kk)
                                      : (g1w + (ng - 512) * 4096 + 2048 + kb + kk);
        cp4(Wb + kk * 257 + n, src);
    }
    CP_COMMIT();
}

__global__ __launch_bounds__(512, 1)
void uv_gemm_kernel(const float* __restrict__ x, const float* __restrict__ g1w,
                    const float* __restrict__ g1b) {
    extern __shared__ float sm[];
    float* As = sm;                  // 2 x [32][130]
    float* Ws = sm + 2 * 4160;       // 2 x [32][257]
    int t = threadIdx.x;
    int ty = t >> 5, tx = t & 31;
    int m0 = blockIdx.x * 128;
    int n0 = blockIdx.y * 256;
    ull acc[4][8];
    zero_acc(acc);

    uv_issue(As, Ws, x, g1w, m0, n0, 0, t);
    uv_issue(As, Ws, x, g1w, m0, n0, 1, t);

    for (int kc = 0; kc < 64; ++kc) {
        if (kc < 63) { CP_WAIT1(); } else { CP_WAIT0(); }
        __syncthreads();                                   // chunk kc visible
        micro32(As + (kc & 1) * 4160, 130, Ws + (kc & 1) * 8224, ty, tx, acc);
        __syncthreads();                                   // buffers kc free
        if (kc + 2 < 64) uv_issue(As, Ws, x, g1w, m0, n0, kc + 2, t);
    }
#pragma unroll
    for (int j = 0; j < 8; ++j) {
        int col = n0 + tx + 32 * j;
        float bias = (col < 512) ? g1b[col] : 0.f;         // fold g1_b into U
#pragma unroll
        for (int p = 0; p < 4; ++p) {
            float2 v = unpack2(acc[p][j]);
            int r = m0 + ty * 8 + 2 * p;
            d_UV[r * 1024 + col]       = v.x + bias;
            d_UV[(r + 1) * 1024 + col] = v.y + bias;
        }
    }
}

// ---------------- pairwise MLP: global chunk schedule over 3 layers ----------------
// chunks 0..15 -> g2 (ldk 512), 16..23 -> g3 (ldk 256), 24..31 -> g4 (ldk 256)
__device__ __forceinline__ void pw_issue_w(int g, float* Ws,
                                           const float* __restrict__ g2w,
                                           const float* __restrict__ g3w,
                                           const float* __restrict__ g4w, int t) {
    const float* src; int ldk, kb;
    if (g < 16)      { src = g2w; ldk = 512; kb = 32 * g; }
    else if (g < 24) { src = g3w; ldk = 256; kb = 32 * (g - 16); }
    else             { src = g4w; ldk = 256; kb = 32 * (g - 24); }
    cp_w_chunk(Ws + (g & 1) * 8224, src, ldk, kb, t);
    CP_COMMIT();
}

__global__ __launch_bounds__(512, 1)
void pairwise_kernel(const float* __restrict__ g2w, const float* __restrict__ g2b,
                     const float* __restrict__ g3w, const float* __restrict__ g3b,
                     const float* __restrict__ g4w, const float* __restrict__ g4b) {
    extern __shared__ float sm[];
    float* As   = sm;                        // 2 x [32][130]  (also reduction scratch)
    float* Ws   = sm + 2 * 4160;             // 2 x [32][257]
    float* Hbuf = sm + 2 * 4160 + 2 * 8224;  // [256 cols][130 rows]
    int t = threadIdx.x;
    int ty = t >> 5, tx = t & 31;
    int atile = blockIdx.x;                  // 8 a-tiles of 4
    int b = blockIdx.y;                      // 128 batches
    int a0 = atile * 4;

    ull acc[4][8];
    float ua[8], va[8];                      // layer-2 A prefetch regs

    // ---- prologue: A chunks 0,1 direct to smem; W groups G0,G1 ----
#pragma unroll
    for (int c = 0; c < 2; ++c) {
#pragma unroll
        for (int i = 0; i < 8; ++i) {
            int e = i * 512 + t;
            int kk = e & 31, row = e >> 5;
            int p = row & 31, a = a0 + (row >> 5);
            float u = d_UV[(b * 32 + p) * 1024 + c * 32 + kk];
            float v = d_UV[(b * 32 + a) * 1024 + 512 + c * 32 + kk];
            As[c * 4160 + kk * 130 + row] = fmaxf(u + v, 0.f);
        }
    }
    pw_issue_w(0, Ws, g2w, g3w, g4w, t);
    pw_issue_w(1, Ws, g2w, g3w, g4w, t);

    // ---- layer 2: chunks 0..15, A = relu(U+V) reg-prefetched 2 ahead ----
    zero_acc(acc);
    for (int g = 0; g < 16; ++g) {
        CP_WAIT1();
        __syncthreads();                                   // W chunk g + A chunk g visible
        if (g + 2 < 16) {                                  // LDG next-next A (latency under micro32)
#pragma unroll
            for (int i = 0; i < 8; ++i) {
                int e = i * 512 + t;
                int kk = e & 31, row = e >> 5;
                int p = row & 31, a = a0 + (row >> 5);
                ua[i] = d_UV[(b * 32 + p) * 1024 + (g + 2) * 32 + kk];
                va[i] = d_UV[(b * 32 + a) * 1024 + 512 + (g + 2) * 32 + kk];
            }
        }
        micro32(As + (g & 1) * 4160, 130, Ws + (g & 1) * 8224, ty, tx, acc);
        __syncthreads();                                   // buffers g free
        if (g + 2 < 16) {
#pragma unroll
            for (int i = 0; i < 8; ++i) {
                int e = i * 512 + t;
                int kk = e & 31, row = e >> 5;
                As[(g & 1) * 4160 + kk * 130 + row] = fmaxf(ua[i] + va[i], 0.f);
            }
        }
        pw_issue_w(g + 2, Ws, g2w, g3w, g4w, t);           // g+2 in [2..17]: crosses into g3
    }
    // epilogue2 -> Hbuf
#pragma unroll
    for (int j = 0; j < 8; ++j) {
        int col = tx + 32 * j;
        float bias = g2b[col];
#pragma unroll
        for (int p = 0; p < 4; ++p) {
            float2 v = unpack2(acc[p][j]);
            *reinterpret_cast<ull*>(Hbuf + col * 130 + ty * 8 + 2 * p) =
                pack2(fmaxf(v.x + bias, 0.f), fmaxf(v.y + bias, 0.f));
        }
    }
    __syncthreads();

    // ---- layer 3: chunks 16..23, A = Hbuf in place ----
    zero_acc(acc);
    for (int g = 16; g < 24; ++g) {
        CP_WAIT1();
        __syncthreads();
        micro32(Hbuf + (g - 16) * 32 * 130, 130, Ws + (g & 1) * 8224, ty, tx, acc);
        __syncthreads();
        pw_issue_w(g + 2, Ws, g2w, g3w, g4w, t);           // g+2 in [18..25]: crosses into g4
    }
    // epilogue3 -> Hbuf (all reads done: last loop sync)
#pragma unroll
    for (int j = 0; j < 8; ++j) {
        int col = tx + 32 * j;
        float bias = g3b[col];
#pragma unroll
        for (int p = 0; p < 4; ++p) {
            float2 v = unpack2(acc[p][j]);
            *reinterpret_cast<ull*>(Hbuf + col * 130 + ty * 8 + 2 * p) =
                pack2(fmaxf(v.x + bias, 0.f), fmaxf(v.y + bias, 0.f));
        }
    }
    __syncthreads();

    // ---- layer 4: chunks 24..31, reduce rows ----
    zero_acc(acc);
    for (int g = 24; g < 32; ++g) {
        if (g < 31) { CP_WAIT1(); } else { CP_WAIT0(); }
        __syncthreads();
        micro32(Hbuf + (g - 24) * 32 * 130, 130, Ws + (g & 1) * 8224, ty, tx, acc);
        __syncthreads();
        if (g + 2 < 32) pw_issue_w(g + 2, Ws, g2w, g3w, g4w, t);
    }
    // per-thread partial row-sum of relu(acc + g4_b)
#pragma unroll
    for (int j = 0; j < 8; ++j) {
        int col = tx + 32 * j;
        float bias = g4b[col];
        float s = 0.f;
#pragma unroll
        for (int p = 0; p < 4; ++p) {
            float2 v = unpack2(acc[p][j]);
            s += fmaxf(v.x + bias, 0.f) + fmaxf(v.y + bias, 0.f);
        }
        As[ty * 256 + col] = s;                            // As region free now
    }
    __syncthreads();
    if (t < 256) {
        float s = 0.f;
#pragma unroll
        for (int ty2 = 0; ty2 < 16; ++ty2) s += As[ty2 * 256 + t];
        d_xgp[(atile * 128 + b) * 256 + t] = s;
    }
}

// ---------------- head ----------------
// fused: xg reduction + f1 + concat + fc2  (per batch row)
__global__ void f12_kernel(const float* __restrict__ f1w, const float* __restrict__ f1b,
                           const float* __restrict__ fc2w, const float* __restrict__ fc2b) {
    __shared__ float sxg[256];
    __shared__ float sxf[512];
    int b = blockIdx.x, t = threadIdx.x;   // 256 threads
    float s = 0.f;
#pragma unroll
    for (int at = 0; at < 8; ++at) s += d_xgp[(at * 128 + b) * 256 + t];
    sxg[t] = s;
    __syncthreads();
    float acc = f1b[t];
    const float4* wr = reinterpret_cast<const float4*>(f1w + t * 256);
#pragma unroll 8
    for (int k4 = 0; k4 < 64; ++k4) {
        float4 w = wr[k4];
        acc += sxg[4 * k4] * w.x + sxg[4 * k4 + 1] * w.y
             + sxg[4 * k4 + 2] * w.z + sxg[4 * k4 + 3] * w.w;
    }
    sxf[t]       = fmaxf(acc, 0.f);
    sxf[256 + t] = d_glbl[b * 256 + t];
    __syncthreads();
    float acc2 = fc2b[t];
    const float4* wr2 = reinterpret_cast<const float4*>(fc2w + t * 512);
#pragma unroll 8
    for (int k4 = 0; k4 < 128; ++k4) {
        float4 wv = wr2[k4];
        acc2 += sxf[4 * k4] * wv.x + sxf[4 * k4 + 1] * wv.y
              + sxf[4 * k4 + 2] * wv.z + sxf[4 * k4 + 3] * wv.w;
    }
    d_z2[b * 256 + t] = acc2;
}

__global__ void bn2_kernel(const float* __restrict__ g, const float* __restrict__ bb) {
    __shared__ float red[128];
    int o = blockIdx.x, r = threadIdx.x;   // 256 cols x 128 rows
    float v = d_z2[r * 256 + o];
    red[r] = v;
    __syncthreads();
    for (int s = 64; s > 0; s >>= 1) { if (r < s) red[r] += red[r + s]; __syncthreads(); }
    float mu = red[0] * (1.f / 128.f);
    __syncthreads();
    float dlt = v - mu;
    red[r] = dlt * dlt;
    __syncthreads();
    for (int s = 64; s > 0; s >>= 1) { if (r < s) red[r] += red[r + s]; __syncthreads(); }
    float var = red[0] * (1.f / 128.f);
    d_y2[r * 256 + o] = fmaxf(dlt * rsqrtf(var + 1e-5f) * g[o] + bb[o], 0.f);
}

__global__ void fc3_kernel(const float* __restrict__ w, const float* __restrict__ bb) {
    __shared__ float sx[256];
    int b = blockIdx.x, t = threadIdx.x;   // 128 threads
    sx[t] = d_y2[b * 256 + t];
    sx[t + 128] = d_y2[b * 256 + 128 + t];
    __syncthreads();
    float acc = bb[t];
    const float4* wr = reinterpret_cast<const float4*>(w + t * 256);
#pragma unroll 8
    for (int k4 = 0; k4 < 64; ++k4) {
        float4 wv = wr[k4];
        acc += sx[4 * k4] * wv.x + sx[4 * k4 + 1] * wv.y
             + sx[4 * k4 + 2] * wv.z + sx[4 * k4 + 3] * wv.w;
    }
    d_z3[b * 128 + t] = acc;
}

__global__ void bn3_kernel(const float* __restrict__ g, const float* __restrict__ bb,
                           float* __restrict__ out) {
    __shared__ float red[128];
    int o = blockIdx.x, r = threadIdx.x;   // 128 cols x 128 rows
    float v = d_z3[r * 128 + o];
    red[r] = v;
    __syncthreads();
    for (int s = 64; s > 0; s >>= 1) { if (r < s) red[r] += red[r + s]; __syncthreads(); }
    float mu = red[0] * (1.f / 128.f);
    __syncthreads();
    float dlt = v - mu;
    red[r] = dlt * dlt;
    __syncthreads();
    for (int s = 64; s > 0; s >>= 1) { if (r < s) red[r] += red[r + s]; __syncthreads(); }
    float var = red[0] * (1.f / 128.f);
    out[r * 128 + o] = fmaxf(dlt * rsqrtf(var + 1e-5f) * g[o] + bb[o], 0.f);
}

// ---------------- launch ----------------
extern "C" void kernel_launch(void* const* d_in, const int* in_sizes, int n_in,
                              void* d_out, int out_size) {
    const float* x      = (const float*)d_in[0];
    const float* conv_w = (const float*)d_in[1];
    const float* conv_b = (const float*)d_in[2];
    const float* g1_w   = (const float*)d_in[3];
    const float* g1_b   = (const float*)d_in[4];
    const float* g2_w   = (const float*)d_in[5];
    const float* g2_b   = (const float*)d_in[6];
    const float* g3_w   = (const float*)d_in[7];
    const float* g3_b   = (const float*)d_in[8];
    const float* g4_w   = (const float*)d_in[9];
    const float* g4_b   = (const float*)d_in[10];
    const float* f1_w   = (const float*)d_in[11];
    const float* f1_b   = (const float*)d_in[12];
    const float* fc2_w  = (const float*)d_in[13];
    const float* fc2_b  = (const float*)d_in[14];
    const float* bn2_g  = (const float*)d_in[15];
    const float* bn2_b  = (const float*)d_in[16];
    const float* fc3_w  = (const float*)d_in[17];
    const float* fc3_b  = (const float*)d_in[18];
    const float* bn3_g  = (const float*)d_in[19];
    const float* bn3_b  = (const float*)d_in[20];
    float* out = (float*)d_out;

    const int UV_SMEM = (2 * 4160 + 2 * 8224) * 4;              // 99072 B
    const int PW_SMEM = (2 * 4160 + 2 * 8224 + 256 * 130) * 4;  // 232192 B
    cudaFuncSetAttribute(uv_gemm_kernel, cudaFuncAttributeMaxDynamicSharedMemorySize, UV_SMEM);
    cudaFuncSetAttribute(pairwise_kernel, cudaFuncAttributeMaxDynamicSharedMemorySize, PW_SMEM);

    glbl_kernel<<<128, 256>>>(x, conv_w, conv_b);
    uv_gemm_kernel<<<dim3(32, 4), 512, UV_SMEM>>>(x, g1_w, g1_b);
    pairwise_kernel<<<dim3(8, 128), 512, PW_SMEM>>>(g2_w, g2_b, g3_w, g3_b, g4_w, g4_b);
    f12_kernel<<<128, 256>>>(f1_w, f1_b, fc2_w, fc2_b);
    bn2_kernel<<<256, 128>>>(bn2_g, bn2_b);
    fc3_kernel<<<128, 128>>>(fc3_w, fc3_b);
    bn3_kernel<<<128, 128>>>(bn3_g, bn3_b, out);
}